// round 12
// baseline (speedup 1.0000x reference)
#include <cuda_runtime.h>
#include <math.h>

// Problem constants
#define BATCH 128
#define HDIM  512
#define IDIM  512
#define NG    (6 * HDIM)   // 3072 gate columns
#define INV_SQRT_H 0.04419417382415922f  // 1/sqrt(512)

// Output layout: concat(h_t [B,H], C_t [B,H,H], m_t [B,H], n_t [B,H])
#define OUT_H 0
#define OUT_C (BATCH * HDIM)                                // 65536
#define OUT_M (OUT_C + (long)BATCH * HDIM * HDIM)           // 33619968
#define OUT_N (OUT_M + BATCH * HDIM)                        // 33685504

#define NSPLIT 4

// Scratch (device globals — no allocation allowed)
__device__ float g_part[NSPLIT][BATCH * NG];  // split-K partial gate sums
__device__ float g_q[BATCH * HDIM];      // biased q (for stream kernel)
__device__ float g_f[BATCH * HDIM];
__device__ float g_add[BATCH * HDIM];
__device__ float g_o[BATCH * HDIM];
__device__ float g_sumq[BATCH];
__device__ float g_invden[BATCH];

// ---------------------------------------------------------------------------
// K1: partial gates = x @ W^T, split-K=4, fp32 FFMA.
// 4x8 register tile, 128 threads, BM=64, BN=64, BK=16.
// Smem intensity 1.5 B/FMA-lane (48B per 32 FMAs) — down 25% from R8's 2.0,
// which the L1%-x-dur invariant says is the binding resource. Loader mapping
// puts lane==row so the transpose scatter is bank-conflict-free (no padding).
// grid (48,2,4) = 384 blocks x 4 warps = 10.4 warps/SM (proven sufficient).
// ---------------------------------------------------------------------------
#define SBM 64
#define SBN 64
#define SBK 16
#define KSPLIT 128   // IDIM / NSPLIT

__global__ __launch_bounds__(128, 5) void gemm_splitk_kernel(
    const float* __restrict__ x,    // [128,512]
    const float* __restrict__ Wm)   // [3072,512]
{
    __shared__ float sA[SBK][SBM];  // no pad: scatter is lane==row (conflict-free)
    __shared__ float sB[SBK][SBN];

    int tid = threadIdx.x;          // 0..127
    int n0 = blockIdx.x * SBN;
    int m0 = blockIdx.y * SBM;
    int kbase = blockIdx.z * KSPLIT;
    float* dst = &g_part[blockIdx.z][0];

    int tx = tid & 7;               // 8 n-groups * 8 = 64 cols
    int ty = tid >> 3;              // 16 m-groups * 4 = 64 rows

    // Loaders: each thread owns one row (lane==row&31 -> bank-distinct stores)
    // and an 8-wide k-chunk: threads 0-63 cover k[0:8), 64-127 cover k[8:16).
    int lrow = tid & 63;
    int lk   = (tid >> 6) * 8;
    const float* Aptr = x  + (long)(m0 + lrow) * IDIM + kbase + lk;
    const float* Bptr = Wm + (long)(n0 + lrow) * IDIM + kbase + lk;

    float acc[4][8];
#pragma unroll
    for (int i = 0; i < 4; i++)
#pragma unroll
        for (int j = 0; j < 8; j++) acc[i][j] = 0.f;

    // register prefetch of first tile (2 float4 per operand per thread)
    float4 pa0 = *reinterpret_cast<const float4*>(Aptr);
    float4 pa1 = *reinterpret_cast<const float4*>(Aptr + 4);
    float4 pb0 = *reinterpret_cast<const float4*>(Bptr);
    float4 pb1 = *reinterpret_cast<const float4*>(Bptr + 4);

    for (int kt = 0; kt < KSPLIT; kt += SBK) {
        // conflict-free transpose scatter (bank = f(lrow) distinct per lane)
        sA[lk + 0][lrow] = pa0.x; sA[lk + 1][lrow] = pa0.y;
        sA[lk + 2][lrow] = pa0.z; sA[lk + 3][lrow] = pa0.w;
        sA[lk + 4][lrow] = pa1.x; sA[lk + 5][lrow] = pa1.y;
        sA[lk + 6][lrow] = pa1.z; sA[lk + 7][lrow] = pa1.w;
        sB[lk + 0][lrow] = pb0.x; sB[lk + 1][lrow] = pb0.y;
        sB[lk + 2][lrow] = pb0.z; sB[lk + 3][lrow] = pb0.w;
        sB[lk + 4][lrow] = pb1.x; sB[lk + 5][lrow] = pb1.y;
        sB[lk + 6][lrow] = pb1.z; sB[lk + 7][lrow] = pb1.w;
        __syncthreads();

        if (kt + SBK < KSPLIT) {   // prefetch next tile during compute
            pa0 = *reinterpret_cast<const float4*>(Aptr + kt + SBK);
            pa1 = *reinterpret_cast<const float4*>(Aptr + kt + SBK + 4);
            pb0 = *reinterpret_cast<const float4*>(Bptr + kt + SBK);
            pb1 = *reinterpret_cast<const float4*>(Bptr + kt + SBK + 4);
        }

#pragma unroll
        for (int k = 0; k < SBK; k++) {
            float4 a  = *reinterpret_cast<const float4*>(&sA[k][ty * 4]);      // broadcast (4 addrs/warp)
            float4 b0 = *reinterpret_cast<const float4*>(&sB[k][tx * 8]);      // 8 addrs, 128B -> 1 wf
            float4 b1 = *reinterpret_cast<const float4*>(&sB[k][tx * 8 + 4]);
            float av[4] = {a.x, a.y, a.z, a.w};
            float bv[8] = {b0.x, b0.y, b0.z, b0.w, b1.x, b1.y, b1.z, b1.w};
#pragma unroll
            for (int i = 0; i < 4; i++)
#pragma unroll
                for (int j = 0; j < 8; j++) acc[i][j] += av[i] * bv[j];
        }
        __syncthreads();
    }

#pragma unroll
    for (int i = 0; i < 4; i++) {
        int m = m0 + ty * 4 + i;
        float4 o0 = make_float4(acc[i][0], acc[i][1], acc[i][2], acc[i][3]);
        float4 o1 = make_float4(acc[i][4], acc[i][5], acc[i][6], acc[i][7]);
        *reinterpret_cast<float4*>(dst + (long)m * NG + n0 + tx * 8)     = o0;
        *reinterpret_cast<float4*>(dst + (long)m * NG + n0 + tx * 8 + 4) = o1;
    }
}

// ---------------------------------------------------------------------------
// K2: fused partial-sum (4 splits) + bias + gate elementwise + per-batch
// reductions. One block (512 thr) per batch.
// ---------------------------------------------------------------------------
__global__ __launch_bounds__(512) void gatered_kernel(
    const float* __restrict__ m_prev,
    const float* __restrict__ n_prev,
    const float* __restrict__ bias,
    float* __restrict__ out)
{
    int b = blockIdx.x;
    int h = threadIdx.x;           // 0..511
    int idx = b * HDIM + h;
    long base = (long)b * NG;

    float gv[6];
#pragma unroll
    for (int s = 0; s < 6; s++) {
        int col = s * HDIM + h;
        float v = (g_part[0][base + col] + g_part[1][base + col])
                + (g_part[2][base + col] + g_part[3][base + col]);
        gv[s] = v + bias[col];
    }
    float ig = gv[0], fg = gv[1], og = gv[2], qv = gv[3], kg = gv[4], vg = gv[5];

    float mp = m_prev[idx];
    float mt = fmaxf(fg + mp, ig);
    float it = expf(ig - mt);
    float ft = expf(fg + mp - mt);
    float kt = INV_SQRT_H * kg;
    float nt = ft * n_prev[idx] + it * kt;

    out[OUT_M + idx] = mt;
    out[OUT_N + idx] = nt;
    g_q[idx]   = qv;
    g_f[idx]   = ft;
    g_add[idx] = it * vg * kt;
    g_o[idx]   = 1.f / (1.f + expf(-og));

    // block reductions: sq = sum(q), nq = dot(n_t, q)
    float sq = qv;
    float nq = nt * qv;
    for (int s = 16; s; s >>= 1) {
        sq += __shfl_xor_sync(0xffffffffu, sq, s);
        nq += __shfl_xor_sync(0xffffffffu, nq, s);
    }
    __shared__ float s1[16], s2[16];
    int warp = h >> 5, lane = h & 31;
    if (lane == 0) { s1[warp] = sq; s2[warp] = nq; }
    __syncthreads();
    if (warp == 0) {
        sq = (lane < 16) ? s1[lane] : 0.f;
        nq = (lane < 16) ? s2[lane] : 0.f;
        for (int s = 8; s; s >>= 1) {
            sq += __shfl_xor_sync(0xffffffffu, sq, s);
            nq += __shfl_xor_sync(0xffffffffu, nq, s);
        }
        if (lane == 0) {
            g_sumq[b]   = sq;
            g_invden[b] = 1.f / fmaxf(fabsf(nq), 1e-6f);
        }
    }
}

// ---------------------------------------------------------------------------
// K3: THE bandwidth kernel (1 row/warp — measured best). C_t = f*C_prev + add,
// fused Cq = f*dot(row,q) + add*sum_q, h_t direct.
// ---------------------------------------------------------------------------
__global__ __launch_bounds__(256) void stream_C_kernel(
    const float* __restrict__ Cprev,
    float* __restrict__ out)
{
    __shared__ float sq[HDIM];
    int b  = blockIdx.x >> 6;     // 64 blocks per batch (512 rows / 8)
    int rg = blockIdx.x & 63;
    int tid = threadIdx.x;

    // load biased q[b,:] into smem (float2 x 256 threads)
    const float* qrow = g_q + (long)b * HDIM;
    reinterpret_cast<float2*>(sq)[tid] = reinterpret_cast<const float2*>(qrow)[tid];
    __syncthreads();

    int warp = tid >> 5, lane = tid & 31;
    int i = rg * 8 + warp;
    int bh = b * HDIM + i;
    long rowoff = ((long)b * HDIM + i) * HDIM;

    float fv = g_f[bh];
    float av = g_add[bh];

    const float4* src = reinterpret_cast<const float4*>(Cprev + rowoff);
    float4*       dst = reinterpret_cast<float4*>(out + OUT_C + rowoff);
    const float4* qsv = reinterpret_cast<const float4*>(sq);

    // batch the 4 independent 16B loads first (MLP), then compute+store
    float4 c[4], qv[4];
#pragma unroll
    for (int u = 0; u < 4; u++) c[u] = __ldcs(&src[lane + u * 32]);
#pragma unroll
    for (int u = 0; u < 4; u++) qv[u] = qsv[lane + u * 32];

    float dot = 0.f;
#pragma unroll
    for (int u = 0; u < 4; u++) {
        dot += c[u].x * qv[u].x + c[u].y * qv[u].y
             + c[u].z * qv[u].z + c[u].w * qv[u].w;
        float4 o;
        o.x = fv * c[u].x + av;
        o.y = fv * c[u].y + av;
        o.z = fv * c[u].z + av;
        o.w = fv * c[u].w + av;
        __stcs(&dst[lane + u * 32], o);
    }
    for (int s = 16; s; s >>= 1) dot += __shfl_xor_sync(0xffffffffu, dot, s);
    if (lane == 0) {
        float cq = fv * dot + av * g_sumq[b];
        out[OUT_H + bh] = g_o[bh] * cq * g_invden[b];
    }
}

// ---------------------------------------------------------------------------
// Launch. Inputs (metadata order): x, h_prev, C_prev, m_prev, n_prev, W, b
// ---------------------------------------------------------------------------
extern "C" void kernel_launch(void* const* d_in, const int* in_sizes, int n_in,
                              void* d_out, int out_size)
{
    const float* x      = (const float*)d_in[0];
    // d_in[1] = h_prev (unused by reference)
    const float* C_prev = (const float*)d_in[2];
    const float* m_prev = (const float*)d_in[3];
    const float* n_prev = (const float*)d_in[4];
    const float* W      = (const float*)d_in[5];
    const float* bias   = (const float*)d_in[6];
    float* out = (float*)d_out;

    // K1: split-K=4 fp32 GEMM, 4x8 reg tile (384 blocks x 128 threads)
    dim3 ggrid(NG / SBN, BATCH / SBM, NSPLIT);
    gemm_splitk_kernel<<<ggrid, 128>>>(x, W);

    // K2: fused 4-way split sum + bias + gate elementwise + reductions
    gatered_kernel<<<BATCH, 512>>>(m_prev, n_prev, bias, out);

    // K3: C stream (1 row/warp) + fused Cq + h_t
    stream_C_kernel<<<BATCH * (HDIM / 8), 256>>>(C_prev, out);
}

// round 13
// speedup vs baseline: 1.0935x; 1.0935x over previous
#include <cuda_runtime.h>
#include <math.h>

// Problem constants
#define BATCH 128
#define HDIM  512
#define IDIM  512
#define NG    (6 * HDIM)   // 3072 gate columns
#define INV_SQRT_H 0.04419417382415922f  // 1/sqrt(512)

// Output layout: concat(h_t [B,H], C_t [B,H,H], m_t [B,H], n_t [B,H])
#define OUT_H 0
#define OUT_C (BATCH * HDIM)                                // 65536
#define OUT_M (OUT_C + (long)BATCH * HDIM * HDIM)           // 33619968
#define OUT_N (OUT_M + BATCH * HDIM)                        // 33685504

#define NSPLIT 8

// Scratch (device globals — no allocation allowed)
__device__ float g_part[NSPLIT][BATCH * NG];  // split-K partial gate sums
__device__ float g_q[BATCH * HDIM];      // biased q (for stream kernel)
__device__ float g_f[BATCH * HDIM];
__device__ float g_add[BATCH * HDIM];
__device__ float g_o[BATCH * HDIM];
__device__ float g_sumq[BATCH];
__device__ float g_invden[BATCH];

// ---------------------------------------------------------------------------
// K1: partial gates = x @ W^T, split-K=8, fp32 FFMA.
// 8x8 register tile, 128 threads, BM=128 (full batch), BN=64, BK=8.
// Per warp-k: 64 FFMA instrs (32 SM-cyc of FFMA pipe) vs 4 LDS.128
// (<=16 wavefront-cyc) -> 2:1 fma:smem headroom, vs the 1:1 co-saturation
// that pinned the 4x4 config at 20us. 64 independent FMAs per k self-hide
// LDS latency. grid (48,1,8)=384 blocks x 4 warps = 10.4 warps/SM.
// ---------------------------------------------------------------------------
#define GBM 128
#define GBN 64
#define GBK 8
#define KSPLIT 64    // IDIM / NSPLIT

__global__ __launch_bounds__(128) void gemm_splitk_kernel(
    const float* __restrict__ x,    // [128,512]
    const float* __restrict__ Wm)   // [3072,512]
{
    __shared__ float sA[GBK][GBM];  // 4KB ; scatter lane==row -> conflict-free
    __shared__ float sB[GBK][GBN];  // 2KB

    int tid = threadIdx.x;          // 0..127
    int n0 = blockIdx.x * GBN;
    int kbase = blockIdx.z * KSPLIT;
    float* dst = &g_part[blockIdx.z][0];

    int tx = tid & 7;               // 8 n-groups * 8 = 64 cols
    int ty = tid >> 3;              // 16 m-groups * 8 = 128 rows

    // A loader: thread tid owns row tid, full 8-wide k chunk (2 float4)
    const float* Aptr = x + (long)tid * IDIM + kbase;
    // B loader: 64 rows x 8 k = 512 floats; thread -> row tid&63, k-half (tid>>6)*4
    int brow = tid & 63, bkq = (tid >> 6) * 4;
    const float* Bptr = Wm + (long)(n0 + brow) * IDIM + kbase + bkq;

    float acc[8][8];
#pragma unroll
    for (int i = 0; i < 8; i++)
#pragma unroll
        for (int j = 0; j < 8; j++) acc[i][j] = 0.f;

    // register prefetch of first tile
    float4 pa0 = *reinterpret_cast<const float4*>(Aptr);
    float4 pa1 = *reinterpret_cast<const float4*>(Aptr + 4);
    float4 pb  = *reinterpret_cast<const float4*>(Bptr);

    for (int kt = 0; kt < KSPLIT; kt += GBK) {
        // conflict-free transpose scatter (bank = lane for both tiles)
        sA[0][tid] = pa0.x; sA[1][tid] = pa0.y;
        sA[2][tid] = pa0.z; sA[3][tid] = pa0.w;
        sA[4][tid] = pa1.x; sA[5][tid] = pa1.y;
        sA[6][tid] = pa1.z; sA[7][tid] = pa1.w;
        sB[bkq + 0][brow] = pb.x; sB[bkq + 1][brow] = pb.y;
        sB[bkq + 2][brow] = pb.z; sB[bkq + 3][brow] = pb.w;
        __syncthreads();

        if (kt + GBK < KSPLIT) {   // prefetch next tile during compute
            pa0 = *reinterpret_cast<const float4*>(Aptr + kt + GBK);
            pa1 = *reinterpret_cast<const float4*>(Aptr + kt + GBK + 4);
            pb  = *reinterpret_cast<const float4*>(Bptr + kt + GBK);
        }

#pragma unroll
        for (int k = 0; k < GBK; k++) {
            float4 a0 = *reinterpret_cast<const float4*>(&sA[k][ty * 8]);
            float4 a1 = *reinterpret_cast<const float4*>(&sA[k][ty * 8 + 4]);
            float4 b0 = *reinterpret_cast<const float4*>(&sB[k][tx * 8]);
            float4 b1 = *reinterpret_cast<const float4*>(&sB[k][tx * 8 + 4]);
            float av[8] = {a0.x, a0.y, a0.z, a0.w, a1.x, a1.y, a1.z, a1.w};
            float bv[8] = {b0.x, b0.y, b0.z, b0.w, b1.x, b1.y, b1.z, b1.w};
#pragma unroll
            for (int i = 0; i < 8; i++)
#pragma unroll
                for (int j = 0; j < 8; j++) acc[i][j] += av[i] * bv[j];
        }
        __syncthreads();
    }

#pragma unroll
    for (int i = 0; i < 8; i++) {
        int m = ty * 8 + i;
        float4 o0 = make_float4(acc[i][0], acc[i][1], acc[i][2], acc[i][3]);
        float4 o1 = make_float4(acc[i][4], acc[i][5], acc[i][6], acc[i][7]);
        *reinterpret_cast<float4*>(dst + (long)m * NG + n0 + tx * 8)     = o0;
        *reinterpret_cast<float4*>(dst + (long)m * NG + n0 + tx * 8 + 4) = o1;
    }
}

// ---------------------------------------------------------------------------
// K2: fused partial-sum (8 splits) + bias + gate elementwise + per-batch
// reductions. One block (512 thr) per batch.
// ---------------------------------------------------------------------------
__global__ __launch_bounds__(512) void gatered_kernel(
    const float* __restrict__ m_prev,
    const float* __restrict__ n_prev,
    const float* __restrict__ bias,
    float* __restrict__ out)
{
    int b = blockIdx.x;
    int h = threadIdx.x;           // 0..511
    int idx = b * HDIM + h;
    long base = (long)b * NG;

    float gv[6];
#pragma unroll
    for (int s = 0; s < 6; s++) {
        int col = s * HDIM + h;
        float v = ((g_part[0][base + col] + g_part[1][base + col])
                 + (g_part[2][base + col] + g_part[3][base + col]))
                + ((g_part[4][base + col] + g_part[5][base + col])
                 + (g_part[6][base + col] + g_part[7][base + col]));
        gv[s] = v + bias[col];
    }
    float ig = gv[0], fg = gv[1], og = gv[2], qv = gv[3], kg = gv[4], vg = gv[5];

    float mp = m_prev[idx];
    float mt = fmaxf(fg + mp, ig);
    float it = expf(ig - mt);
    float ft = expf(fg + mp - mt);
    float kt = INV_SQRT_H * kg;
    float nt = ft * n_prev[idx] + it * kt;

    out[OUT_M + idx] = mt;
    out[OUT_N + idx] = nt;
    g_q[idx]   = qv;
    g_f[idx]   = ft;
    g_add[idx] = it * vg * kt;
    g_o[idx]   = 1.f / (1.f + expf(-og));

    // block reductions: sq = sum(q), nq = dot(n_t, q)
    float sq = qv;
    float nq = nt * qv;
    for (int s = 16; s; s >>= 1) {
        sq += __shfl_xor_sync(0xffffffffu, sq, s);
        nq += __shfl_xor_sync(0xffffffffu, nq, s);
    }
    __shared__ float s1[16], s2[16];
    int warp = h >> 5, lane = h & 31;
    if (lane == 0) { s1[warp] = sq; s2[warp] = nq; }
    __syncthreads();
    if (warp == 0) {
        sq = (lane < 16) ? s1[lane] : 0.f;
        nq = (lane < 16) ? s2[lane] : 0.f;
        for (int s = 8; s; s >>= 1) {
            sq += __shfl_xor_sync(0xffffffffu, sq, s);
            nq += __shfl_xor_sync(0xffffffffu, nq, s);
        }
        if (lane == 0) {
            g_sumq[b]   = sq;
            g_invden[b] = 1.f / fmaxf(fabsf(nq), 1e-6f);
        }
    }
}

// ---------------------------------------------------------------------------
// K3: THE bandwidth kernel (UNCHANGED from R8 best: 1 row/warp, 256 thr).
// C_t = f*C_prev + add, fused Cq = f*dot(row,q) + add*sum_q, h_t direct.
// ---------------------------------------------------------------------------
__global__ __launch_bounds__(256) void stream_C_kernel(
    const float* __restrict__ Cprev,
    float* __restrict__ out)
{
    __shared__ float sq[HDIM];
    int b  = blockIdx.x >> 6;     // 64 blocks per batch (512 rows / 8)
    int rg = blockIdx.x & 63;
    int tid = threadIdx.x;

    // load biased q[b,:] into smem (float2 x 256 threads)
    const float* qrow = g_q + (long)b * HDIM;
    reinterpret_cast<float2*>(sq)[tid] = reinterpret_cast<const float2*>(qrow)[tid];
    __syncthreads();

    int warp = tid >> 5, lane = tid & 31;
    int i = rg * 8 + warp;
    int bh = b * HDIM + i;
    long rowoff = ((long)b * HDIM + i) * HDIM;

    float fv = g_f[bh];
    float av = g_add[bh];

    const float4* src = reinterpret_cast<const float4*>(Cprev + rowoff);
    float4*       dst = reinterpret_cast<float4*>(out + OUT_C + rowoff);
    const float4* qsv = reinterpret_cast<const float4*>(sq);

    // batch the 4 independent 16B loads first (MLP), then compute+store
    float4 c[4], qv[4];
#pragma unroll
    for (int u = 0; u < 4; u++) c[u] = __ldcs(&src[lane + u * 32]);
#pragma unroll
    for (int u = 0; u < 4; u++) qv[u] = qsv[lane + u * 32];

    float dot = 0.f;
#pragma unroll
    for (int u = 0; u < 4; u++) {
        dot += c[u].x * qv[u].x + c[u].y * qv[u].y
             + c[u].z * qv[u].z + c[u].w * qv[u].w;
        float4 o;
        o.x = fv * c[u].x + av;
        o.y = fv * c[u].y + av;
        o.z = fv * c[u].z + av;
        o.w = fv * c[u].w + av;
        __stcs(&dst[lane + u * 32], o);
    }
    for (int s = 16; s; s >>= 1) dot += __shfl_xor_sync(0xffffffffu, dot, s);
    if (lane == 0) {
        float cq = fv * dot + av * g_sumq[b];
        out[OUT_H + bh] = g_o[bh] * cq * g_invden[b];
    }
}

// ---------------------------------------------------------------------------
// Launch. Inputs (metadata order): x, h_prev, C_prev, m_prev, n_prev, W, b
// ---------------------------------------------------------------------------
extern "C" void kernel_launch(void* const* d_in, const int* in_sizes, int n_in,
                              void* d_out, int out_size)
{
    const float* x      = (const float*)d_in[0];
    // d_in[1] = h_prev (unused by reference)
    const float* C_prev = (const float*)d_in[2];
    const float* m_prev = (const float*)d_in[3];
    const float* n_prev = (const float*)d_in[4];
    const float* W      = (const float*)d_in[5];
    const float* bias   = (const float*)d_in[6];
    float* out = (float*)d_out;

    // K1: split-K=8 fp32 GEMM, 8x8 reg tile (384 blocks x 128 threads)
    dim3 ggrid(NG / GBN, 1, NSPLIT);
    gemm_splitk_kernel<<<ggrid, 128>>>(x, W);

    // K2: fused 8-way split sum + bias + gate elementwise + reductions
    gatered_kernel<<<BATCH, 512>>>(m_prev, n_prev, bias, out);

    // K3: C stream (1 row/warp) + fused Cq + h_t
    stream_C_kernel<<<BATCH * (HDIM / 8), 256>>>(C_prev, out);
}